// round 3
// baseline (speedup 1.0000x reference)
#include <cuda_runtime.h>

// Levinson-Durbin, one thread per batch (B=65536, M=64).
// R2 change vs R1: __launch_bounds__(128,4) caps regs at 128 so the compiler
// keeps a[64] in registers but re-reads r[] from shared (instead of caching
// all 65 r values in regs -> 239 regs -> occ 12%). Occupancy 2->4 CTAs/SM.
// Dot product uses 4 accumulators to shorten the FFMA dependency chain.

constexpr int M  = 64;
constexpr int NR = M + 1;   // 65 floats per row
constexpr int BT = 128;     // threads (= batches) per block

__global__ __launch_bounds__(BT, 4)
void levdur_kernel(const float* __restrict__ g_r,
                   float* __restrict__ g_out,
                   int nbatch)
{
    __shared__ float sm[BT * NR];   // 33,280 B -> 4 CTAs fit in 228KB
    const int tid = threadIdx.x;
    const long long base  = (long long)blockIdx.x * BT * NR;
    const long long total = (long long)nbatch * NR;

    // Coalesced load: flat copy of this block's 128 rows.
    #pragma unroll
    for (int i = 0; i < NR; ++i) {
        long long idx = base + (long long)i * BT + tid;
        if (idx < total) sm[i * BT + tid] = g_r[idx];
    }
    __syncthreads();

    const int batch = blockIdx.x * BT + tid;
    float* r = &sm[tid * NR];   // private row; stride 65 -> conflict-free

    if (batch < nbatch) {
        float a[NR];            // registers (constant indices via full unroll)
        float E = r[0];

        #pragma unroll
        for (int m = 1; m <= M; ++m) {
            // acc = r[m] + sum_{j=1}^{m-1} a[j] * r[m-j], 4-way ILP split.
            float acc0 = r[m], acc1 = 0.0f, acc2 = 0.0f, acc3 = 0.0f;
            #pragma unroll
            for (int j = 1; j <= m - 1; ++j) {
                switch ((j - 1) & 3) {
                    case 0: acc0 = fmaf(a[j], r[m - j], acc0); break;
                    case 1: acc1 = fmaf(a[j], r[m - j], acc1); break;
                    case 2: acc2 = fmaf(a[j], r[m - j], acc2); break;
                    default: acc3 = fmaf(a[j], r[m - j], acc3); break;
                }
            }
            float num = (acc0 + acc1) + (acc2 + acc3);

            float k = __fdividef(-num, E);
            E = fmaf(-k * k, E, E);              // E *= (1 - k^2)

            // a_new[j] = a[j] + k * a[m-j], symmetric pairs in place.
            #pragma unroll
            for (int i = 1; i < m - i; ++i) {
                float t = a[i];
                a[i]     = fmaf(k, a[m - i], t);
                a[m - i] = fmaf(k, t, a[m - i]);
            }
            if ((m & 1) == 0 && m >= 2) {        // middle element (m even)
                int h = m >> 1;
                a[h] = fmaf(k, a[h], a[h]);
            }
            a[m] = k;
        }

        // Write result into our shared row: [K, a1..aM].
        r[0] = sqrtf(E);
        #pragma unroll
        for (int i = 1; i <= M; ++i) r[i] = a[i];
    }
    __syncthreads();

    // Coalesced store.
    #pragma unroll
    for (int i = 0; i < NR; ++i) {
        long long idx = base + (long long)i * BT + tid;
        if (idx < total) g_out[idx] = sm[i * BT + tid];
    }
}

extern "C" void kernel_launch(void* const* d_in, const int* in_sizes, int n_in,
                              void* d_out, int out_size)
{
    const float* r = (const float*)d_in[0];
    float* out = (float*)d_out;
    int nbatch = in_sizes[0] / NR;           // 65536
    int grid = (nbatch + BT - 1) / BT;       // 512
    levdur_kernel<<<grid, BT>>>(r, out, nbatch);
}